// round 12
// baseline (speedup 1.0000x reference)
#include <cuda_runtime.h>
#include <cuda_fp16.h>
#include <cstdint>

// ---------------- problem constants ----------------
#define B_   8
#define S_   4096
#define D_   2048
#define M_   (B_*S_)        // 32768 tokens
#define E1_  (3*D_)         // 6144
#define NCHUNK 128
#define CHUNKS_S (S_/NCHUNK)   // 32

// ---------------- scratch (device globals) ----------------
__device__ __half g_Qh [67108864];   // fp16 Q (natural layout)
__device__ __half g_Kh [67108864];   // fp16 K
__device__ __half g_Vh [67108864];   // fp16 V
__device__ __half g_Yh [67108864];   // fp16, pair-permuted (GEMM2 A)
__device__ __half g_Xh [67108864];   // fp16(X), pair-permuted
__device__ __half g_W1h[(size_t)E1_ * D_];   // fp16(W_in), pair-permuted
__device__ __half g_W2h[(size_t)D_ * D_];    // fp16(W_out), pair-permuted
__device__ float  g_Apart[(size_t)B_ * NCHUNK * D_];
__device__ float  g_A[B_ * D_];

#define NEG_L2T_OVER_512 (-0.025952563241307517)

// ---------------- PTX helpers ----------------
__device__ __forceinline__ void cp_async16(void* sdst, const void* gsrc) {
    unsigned saddr = (unsigned)__cvta_generic_to_shared(sdst);
    asm volatile("cp.async.cg.shared.global [%0], [%1], 16;" :: "r"(saddr), "l"(gsrc));
}
#define CP_COMMIT() asm volatile("cp.async.commit_group;")
#define CP_WAIT2()  asm volatile("cp.async.wait_group 2;")

__device__ __forceinline__ unsigned pack_h2(float lo, float hi) {
    __half2 h = __floats2half2_rn(lo, hi);
    return *(unsigned*)&h;
}

__device__ __forceinline__ void mma_f16(float c[4], unsigned a0, unsigned a1,
                                        unsigned a2, unsigned a3,
                                        unsigned b0, unsigned b1) {
    asm volatile(
        "mma.sync.aligned.m16n8k16.row.col.f32.f16.f16.f32 "
        "{%0,%1,%2,%3},{%4,%5,%6,%7},{%8,%9},{%0,%1,%2,%3};"
        : "+f"(c[0]), "+f"(c[1]), "+f"(c[2]), "+f"(c[3])
        : "r"(a0), "r"(a1), "r"(a2), "r"(a3), "r"(b0), "r"(b1));
}

// -------- fp32 -> permuted fp16 ------------------------------------------------
// Within each 32-wide k-group: pair p (cols 2p,2p+1), kg = p/8, pp = p%8.
// slot(kg,pp) = (pp&3)*4 + (pp>>2) + 2*kg. Output 16B chunk q of group holds
// kg0 pair q | kg0 pair q+4 | kg1 pair q | kg1 pair q+4.
__global__ __launch_bounds__(256)
void half_perm_kernel(const float* __restrict__ src, __half* __restrict__ dst,
                      int n16)
{
    const int c = blockIdx.x * 256 + threadIdx.x;
    if (c >= n16) return;
    const int row = c >> 8;
    const int cc  = c & 255;
    const int G   = cc >> 2;
    const int q   = cc & 3;
    const float* s = src + (size_t)row * D_ + G * 32 + q * 2;
    uint4 o;
    o.x = pack_h2(s[0],  s[1]);
    o.y = pack_h2(s[8],  s[9]);
    o.z = pack_h2(s[16], s[17]);
    o.w = pack_h2(s[24], s[25]);
    ((uint4*)dst)[c] = o;
}

// ---------------- FP16 GEMM: C[M,N] = A[M,K] * B[N,K]^T (+ epilogue) --------
// 128 threads, 4 warps, warp tile 64x64 (2 warps in M x 2 in N) — halves the
// smem-crossbar bytes per MMA vs the 8-warp 32x64 layout (A/B fragment
// redundancy 2x/2x instead of 2x/4x), so the HMMA pipe is the sole binder.
// BK=32, 4-stage cp.async pipeline, stage indices compile-time.
// MODE 0: A=g_Xh -> g_Qh/g_Kh/g_Vh (fp16), bias=b_in.
// MODE 1: A=g_Yh -> d_out (fp32), epilogue adds b_out + X residual.
#define BM 128
#define BN 128
#define BK 32
#define KT (D_/BK)              // 64
#define NSTG 4
#define STG_U4 512              // uint4 per stage per operand (128 rows x 4)
#define SM_BOFF (NSTG*STG_U4)   // B region after 4 A stages
#define GEMM_SMEM (NSTG*STG_U4*2*16)   // 65536 bytes
#define GTHREADS 128

template <int MODE>
__global__ __launch_bounds__(GTHREADS, 2)
void gemm_f16(const __half* __restrict__ Bg,
              const float* __restrict__ bias,
              const float* __restrict__ Xres,
              float* __restrict__ outParam)
{
    extern __shared__ uint4 sm4[];

    const __half* __restrict__ Ag = (MODE == 0) ? g_Xh : g_Yh;

    const int tid  = threadIdx.x;
    const int lane = tid & 31;
    const int warp = tid >> 5;           // 0..3
    const int wm   = (warp >> 1) * 64;   // 2 warps in M
    const int wn   = (warp & 1) * 64;    // 2 warps in N
    const int gID  = lane >> 2;          // 0..7
    const int tig  = lane & 3;           // 0..3

    const int    blockN = blockIdx.x * BN;
    const size_t blockM = (size_t)blockIdx.y * BM;

    // staging: 512 chunks per operand per stage; thread owns chunks
    // tid + 128*i (i=0..3): row = (tid>>2) + 32*i, 16B-chunk sub = tid&3.
    const int r0  = tid >> 2;            // 0..31
    const int sub = tid & 3;             // 0..3

    // persistent global pointers (halves); advance 32 per staged tile
    const __half* gA = Ag + (blockM + r0) * D_ + sub * 8;
    const __half* gB = Bg + ((size_t)blockN + r0) * D_ + sub * 8;

    // smem chunk offsets within a stage (uint4 units)
    int soff[4];
    #pragma unroll
    for (int i = 0; i < 4; i++) soff[i] = (r0 + 32 * i) * 4 + sub;

    // fragment uint4 offsets within a stage
    int aoff[4][2], boff[8];
    #pragma unroll
    for (int mi = 0; mi < 4; mi++)
        #pragma unroll
        for (int h = 0; h < 2; h++)
            aoff[mi][h] = (wm + mi * 16 + h * 8 + gID) * 4 + tig;
    #pragma unroll
    for (int ni = 0; ni < 8; ni++)
        boff[ni] = (wn + ni * 8 + gID) * 4 + tig;

    float c[4][8][4];
    #pragma unroll
    for (int i = 0; i < 4; i++)
        #pragma unroll
        for (int j = 0; j < 8; j++)
            #pragma unroll
            for (int k = 0; k < 4; k++) c[i][j][k] = 0.f;

    #define STAGE_LOAD(S)                                                    \
        do {                                                                 \
            uint4* sA = sm4 + (S) * STG_U4;                                  \
            uint4* sB = sm4 + SM_BOFF + (S) * STG_U4;                        \
            _Pragma("unroll")                                                \
            for (int i = 0; i < 4; i++) {                                    \
                cp_async16(sA + soff[i], gA + (size_t)(32 * i) * D_);        \
                cp_async16(sB + soff[i], gB + (size_t)(32 * i) * D_);        \
            }                                                                \
            gA += BK; gB += BK;                                              \
        } while (0)

    // uint4 layout: .x = kg0 pair(t), .y = kg0 pair(t+4),
    //               .z = kg1 pair(t), .w = kg1 pair(t+4)
    // Per accumulator: kg0 MMA then kg1 MMA (order identical to prior rounds).
    #define STAGE_COMPUTE(S)                                                 \
        do {                                                                 \
            const uint4* sA = sm4 + (S) * STG_U4;                            \
            const uint4* sB = sm4 + SM_BOFF + (S) * STG_U4;                  \
            uint4 A4[4][2];                                                  \
            _Pragma("unroll")                                                \
            for (int mi = 0; mi < 4; mi++)                                   \
                _Pragma("unroll")                                            \
                for (int h = 0; h < 2; h++)                                  \
                    A4[mi][h] = sA[aoff[mi][h]];                             \
            _Pragma("unroll")                                                \
            for (int ni = 0; ni < 8; ++ni) {                                 \
                const uint4 b = sB[boff[ni]];                                \
                _Pragma("unroll")                                            \
                for (int mi = 0; mi < 4; ++mi)                               \
                    mma_f16(c[mi][ni], A4[mi][0].x, A4[mi][1].x,             \
                            A4[mi][0].y, A4[mi][1].y, b.x, b.y);             \
                _Pragma("unroll")                                            \
                for (int mi = 0; mi < 4; ++mi)                               \
                    mma_f16(c[mi][ni], A4[mi][0].z, A4[mi][1].z,             \
                            A4[mi][0].w, A4[mi][1].w, b.z, b.w);             \
            }                                                                \
        } while (0)

    // prologue: tiles 0..2 -> stages 0..2
    STAGE_LOAD(0); CP_COMMIT();
    STAGE_LOAD(1); CP_COMMIT();
    STAGE_LOAD(2); CP_COMMIT();

    // main: 64 tiles, tile k in stage k%4; at iter k load tile k+3.
    for (int t = 0; t < KT / NSTG; ++t) {
        #pragma unroll
        for (int jj = 0; jj < NSTG; ++jj) {
            const int k = NSTG * t + jj;
            CP_WAIT2();            // tile k's group (committed 3 back) done
            __syncthreads();       // stage (jj+3)%4 fully consumed (tile k-1)
            if (k + 3 < KT) STAGE_LOAD((jj + 3) & 3);
            CP_COMMIT();
            STAGE_COMPUTE(jj);
        }
    }

    #undef STAGE_LOAD
    #undef STAGE_COMPUTE

    // ---------------- epilogue ----------------
    if (MODE == 0) {
        const int sect = blockN >> 11;          // 0:Q 1:K 2:V
        __half* dst = (sect == 0) ? g_Qh : ((sect == 1) ? g_Kh : g_Vh);
        const int colBase = blockN & (D_ - 1);
        #pragma unroll
        for (int mi = 0; mi < 4; ++mi) {
            const size_t rA = blockM + wm + mi * 16 + gID;
            const size_t rB = rA + 8;
            #pragma unroll
            for (int ni = 0; ni < 8; ++ni) {
                const int e  = blockN + wn + ni * 8 + tig * 2;
                const int el = colBase + wn + ni * 8 + tig * 2;
                const float bv0 = __ldg(&bias[e]);
                const float bv1 = __ldg(&bias[e + 1]);
                *(__half2*)(dst + rA * D_ + el) =
                    __floats2half2_rn(c[mi][ni][0] + bv0, c[mi][ni][1] + bv1);
                *(__half2*)(dst + rB * D_ + el) =
                    __floats2half2_rn(c[mi][ni][2] + bv0, c[mi][ni][3] + bv1);
            }
        }
    } else {
        float* dst = outParam;
        const int colBase = blockN;
        #pragma unroll
        for (int mi = 0; mi < 4; ++mi) {
            const size_t rA = blockM + wm + mi * 16 + gID;
            const size_t rB = rA + 8;
            #pragma unroll
            for (int ni = 0; ni < 8; ++ni) {
                const int e  = blockN + wn + ni * 8 + tig * 2;
                const int el = colBase + wn + ni * 8 + tig * 2;
                const float bv0 = __ldg(&bias[e]);
                const float bv1 = __ldg(&bias[e + 1]);
                const float2 x0 = *(const float2*)(Xres + rA * D_ + el);
                const float2 x1 = *(const float2*)(Xres + rB * D_ + el);
                *(float2*)(dst + rA * D_ + el) =
                    make_float2(c[mi][ni][0] + bv0 + x0.x, c[mi][ni][1] + bv1 + x0.y);
                *(float2*)(dst + rB * D_ + el) =
                    make_float2(c[mi][ni][2] + bv0 + x1.x, c[mi][ni][3] + bv1 + x1.y);
            }
        }
    }
}

// -------- reduction stage 1: per (batch, chunk) partial of fm(rope(K)) * V ---
__global__ __launch_bounds__(256)
void reduce_A_kernel()
{
    const int b     = blockIdx.x >> 7;
    const int chunk = blockIdx.x & (NCHUNK - 1);
    const int tid   = threadIdx.x;
    __shared__ float red[8];

    float acc[8];
    #pragma unroll
    for (int j = 0; j < 8; j++) acc[j] = 0.f;

    float invf[2];
    #pragma unroll
    for (int j = 0; j < 2; j++) {
        const int p = tid + 256 * j;
        invf[j] = exp2f((float)p * (float)NEG_L2T_OVER_512);
    }

    const int s0 = chunk * CHUNKS_S;
    for (int s = s0; s < s0 + CHUNKS_S; ++s) {
        const size_t rowoff = ((size_t)b * S_ + s) * D_;
        float kr[8];
        float sq = 0.f;
        #pragma unroll
        for (int j = 0; j < 4; ++j) {
            const int p = tid + 256 * j;
            const float2 kv = __half22float2(*(const __half2*)(g_Kh + rowoff + 2 * p));
            float x0 = kv.x, x1 = kv.y;
            if (j < 2) {
                float sn, cs;
                sincosf((float)s * invf[j], &sn, &cs);
                const float r0 = x0 * cs - x1 * sn;
                const float r1 = x1 * cs + x0 * sn;
                x0 = r0; x1 = r1;
            }
            kr[2 * j] = x0; kr[2 * j + 1] = x1;
            sq = fmaf(x0, x0, fmaf(x1, x1, sq));
        }
        #pragma unroll
        for (int o = 16; o; o >>= 1) sq += __shfl_xor_sync(0xffffffffu, sq, o);
        if ((tid & 31) == 0) red[tid >> 5] = sq;
        __syncthreads();
        const float tot = red[0] + red[1] + red[2] + red[3]
                        + red[4] + red[5] + red[6] + red[7];
        __syncthreads();
        const float inv_n = 1.f / fmaxf(sqrtf(tot), 1e-12f);

        #pragma unroll
        for (int j = 0; j < 4; ++j) {
            const int p = tid + 256 * j;
            const float2 vv = __half22float2(*(const __half2*)(g_Vh + rowoff + 2 * p));
            acc[2 * j]     = fmaf(kr[2 * j]     * inv_n, vv.x, acc[2 * j]);
            acc[2 * j + 1] = fmaf(kr[2 * j + 1] * inv_n, vv.y, acc[2 * j + 1]);
        }
    }
    float* dstp = g_Apart + ((size_t)b * NCHUNK + chunk) * D_;
    #pragma unroll
    for (int j = 0; j < 4; ++j) {
        const int p = tid + 256 * j;
        *(float2*)(dstp + 2 * p) = make_float2(acc[2 * j], acc[2 * j + 1]);
    }
}

// -------- reduction stage 2: fixed-order finalize ----------------------------
__global__ void finalize_A_kernel()
{
    const int i = blockIdx.x * 256 + threadIdx.x;
    const int b = i >> 11;
    const int d = i & (D_ - 1);
    float s = 0.f;
    for (int c = 0; c < NCHUNK; ++c)
        s += g_Apart[((size_t)b * NCHUNK + c) * D_ + d];
    g_A[i] = s;
}

// -------- Yb = fp16(A * rope(Q)), stored pair-PERMUTED for GEMM2 --------------
__global__ __launch_bounds__(256)
void yb_kernel()
{
    const int m = blockIdx.x;
    const int b = m >> 12;
    const int s = m & (S_ - 1);
    const int tid = threadIdx.x;
    const size_t rowoff = (size_t)m * D_;
    const float* Arow = g_A + b * D_;

    #pragma unroll
    for (int j = 0; j < 4; ++j) {
        const int p = tid + 256 * j;          // column pair index (0..1023)
        const float2 q = __half22float2(*(const __half2*)(g_Qh + rowoff + 2 * p));
        float x0 = q.x, x1 = q.y;
        if (j < 2) {
            const float invf = exp2f((float)p * (float)NEG_L2T_OVER_512);
            float sn, cs;
            sincosf((float)s * invf, &sn, &cs);
            const float r0 = x0 * cs - x1 * sn;
            const float r1 = x1 * cs + x0 * sn;
            x0 = r0; x1 = r1;
        }
        const float2 a = *(const float2*)(Arow + 2 * p);
        const int G  = p >> 4;
        const int pg = p & 15;
        const int slot = ((pg & 3) << 2) + ((pg >> 2) & 1) + ((pg >> 3) << 1);
        const unsigned hv = pack_h2(a.x * x0, a.y * x1);
        *(unsigned*)(&g_Yh[rowoff + G * 32 + slot * 2]) = hv;
    }
}

// ---------------- launch ------------------------------------------------------
extern "C" void kernel_launch(void* const* d_in, const int* in_sizes, int n_in,
                              void* d_out, int out_size)
{
    const float* X     = (const float*)d_in[0];   // [8,4096,2048]
    const float* W_in  = (const float*)d_in[1];   // [6144,2048]
    const float* b_in  = (const float*)d_in[2];   // [6144]
    const float* W_out = (const float*)d_in[3];   // [2048,2048]
    const float* b_out = (const float*)d_in[4];   // [2048]
    float* out = (float*)d_out;

    __half* xh; __half* w1h; __half* w2h;
    cudaGetSymbolAddress((void**)&xh,  g_Xh);
    cudaGetSymbolAddress((void**)&w1h, g_W1h);
    cudaGetSymbolAddress((void**)&w2h, g_W2h);

    cudaFuncSetAttribute(gemm_f16<0>, cudaFuncAttributeMaxDynamicSharedMemorySize, GEMM_SMEM);
    cudaFuncSetAttribute(gemm_f16<1>, cudaFuncAttributeMaxDynamicSharedMemorySize, GEMM_SMEM);

    // 0) fp32 -> permuted fp16 operands
    half_perm_kernel<<<(M_ * (D_/8)) / 256, 256>>>(X, xh, M_ * (D_/8));
    half_perm_kernel<<<(E1_ * (D_/8)) / 256, 256>>>(W_in, w1h, E1_ * (D_/8));
    half_perm_kernel<<<(D_ * (D_/8)) / 256, 256>>>(W_out, w2h, D_ * (D_/8));

    // 1) QKV = X @ W_in^T + b_in  ->  g_Qh, g_Kh, g_Vh (fp16)
    gemm_f16<0><<<dim3(E1_ / BN, M_ / BM), GTHREADS, GEMM_SMEM>>>(w1h, b_in, nullptr, nullptr);

    // 2) A = sum_s fm(rope(K)) * V
    reduce_A_kernel<<<B_ * NCHUNK, 256>>>();
    finalize_A_kernel<<<(B_ * D_) / 256, 256>>>();

    // 3) Yb = fp16(A ⊙ rope(Q))  (pair-permuted)
    yb_kernel<<<M_, 256>>>();

    // 4) out = Yb @ W_out^T + b_out + X
    gemm_f16<1><<<dim3(D_ / BN, M_ / BM), GTHREADS, GEMM_SMEM>>>(w2h, b_out, X, out);

    (void)in_sizes; (void)n_in; (void)out_size;
}

// round 13
// speedup vs baseline: 1.0860x; 1.0860x over previous
#include <cuda_runtime.h>
#include <cuda_fp16.h>
#include <cstdint>

// ---------------- problem constants ----------------
#define B_   8
#define S_   4096
#define D_   2048
#define M_   (B_*S_)        // 32768 tokens
#define E1_  (3*D_)         // 6144
#define NCHUNK 128
#define CHUNKS_S (S_/NCHUNK)   // 32

// ---------------- scratch (device globals) ----------------
__device__ __half g_Qh [67108864];   // fp16 Q (natural layout)
__device__ __half g_Kh [67108864];   // fp16 K
__device__ __half g_Vh [67108864];   // fp16 V
__device__ __half g_Yh [67108864];   // fp16, pair-permuted (GEMM2 A)
__device__ __half g_Xh [67108864];   // fp16(X), pair-permuted
__device__ __half g_W1h[(size_t)E1_ * D_];   // fp16(W_in), pair-permuted
__device__ __half g_W2h[(size_t)D_ * D_];    // fp16(W_out), pair-permuted
__device__ float  g_Apart[(size_t)B_ * NCHUNK * D_];
__device__ float  g_A[B_ * D_];

#define NEG_L2T_OVER_512 (-0.025952563241307517)

// ---------------- PTX helpers ----------------
__device__ __forceinline__ void cp_async16(void* sdst, const void* gsrc) {
    unsigned saddr = (unsigned)__cvta_generic_to_shared(sdst);
    asm volatile("cp.async.cg.shared.global [%0], [%1], 16;" :: "r"(saddr), "l"(gsrc));
}
#define CP_COMMIT() asm volatile("cp.async.commit_group;")
#define CP_WAIT2()  asm volatile("cp.async.wait_group 2;")

__device__ __forceinline__ unsigned pack_h2(float lo, float hi) {
    __half2 h = __floats2half2_rn(lo, hi);
    return *(unsigned*)&h;
}

__device__ __forceinline__ void mma_f16(float c[4], unsigned a0, unsigned a1,
                                        unsigned a2, unsigned a3,
                                        unsigned b0, unsigned b1) {
    asm volatile(
        "mma.sync.aligned.m16n8k16.row.col.f32.f16.f16.f32 "
        "{%0,%1,%2,%3},{%4,%5,%6,%7},{%8,%9},{%0,%1,%2,%3};"
        : "+f"(c[0]), "+f"(c[1]), "+f"(c[2]), "+f"(c[3])
        : "r"(a0), "r"(a1), "r"(a2), "r"(a3), "r"(b0), "r"(b1));
}

// -------- fp32 -> permuted fp16 ------------------------------------------------
// Within each 32-wide k-group: pair p (cols 2p,2p+1), kg = p/8, pp = p%8.
// slot(kg,pp) = (pp&3)*4 + (pp>>2) + 2*kg. Output 16B chunk q of group holds
// kg0 pair q | kg0 pair q+4 | kg1 pair q | kg1 pair q+4.
__global__ __launch_bounds__(256)
void half_perm_kernel(const float* __restrict__ src, __half* __restrict__ dst,
                      int n16)
{
    const int c = blockIdx.x * 256 + threadIdx.x;
    if (c >= n16) return;
    const int row = c >> 8;
    const int cc  = c & 255;
    const int G   = cc >> 2;
    const int q   = cc & 3;
    const float* s = src + (size_t)row * D_ + G * 32 + q * 2;
    uint4 o;
    o.x = pack_h2(s[0],  s[1]);
    o.y = pack_h2(s[8],  s[9]);
    o.z = pack_h2(s[16], s[17]);
    o.w = pack_h2(s[24], s[25]);
    ((uint4*)dst)[c] = o;
}

// ---------------- FP16 GEMM: C[M,N] = A[M,K] * B[N,K]^T (+ epilogue) --------
// 256 threads, 8 warps, warp tile 64x32 (2 warps in M x 4 in N): A redundancy
// 2x, B redundancy 2x -> 48 KB smem traffic per CTA-ktile (round-8 layout was
// 64 KB) at the SAME 16 warps/SM occupancy. Two kg-passes with LDS.64
// fragment loads keep live registers under the 128 cap.
// BK=32, 4-stage cp.async pipeline (round-10 staging, byte-identical).
// MODE 0: A=g_Xh -> g_Qh/g_Kh/g_Vh (fp16), bias=b_in.
// MODE 1: A=g_Yh -> d_out (fp32), epilogue adds b_out + X residual.
#define BM 128
#define BN 128
#define BK 32
#define KT (D_/BK)              // 64
#define NSTG 4
#define STG_U4 512              // uint4 per stage per operand (128 rows x 4)
#define SM_BOFF (NSTG*STG_U4)   // B region after 4 A stages
#define GEMM_SMEM (NSTG*STG_U4*2*16)   // 65536 bytes

template <int MODE>
__global__ __launch_bounds__(256, 2)
void gemm_f16(const __half* __restrict__ Bg,
              const float* __restrict__ bias,
              const float* __restrict__ Xres,
              float* __restrict__ outParam)
{
    extern __shared__ uint4 sm4[];

    const __half* __restrict__ Ag = (MODE == 0) ? g_Xh : g_Yh;

    const int tid  = threadIdx.x;
    const int lane = tid & 31;
    const int warp = tid >> 5;           // 0..7
    const int wm   = (warp >> 2) * 64;   // 2 warps in M
    const int wn   = (warp & 3) * 32;    // 4 warps in N
    const int gID  = lane >> 2;          // 0..7
    const int tig  = lane & 3;           // 0..3

    const int    blockN = blockIdx.x * BN;
    const size_t blockM = (size_t)blockIdx.y * BM;

    // staging (round-10 proven): 512 chunks/operand/stage; thread owns
    // chunks tid and tid+256.
    const int ldRow = tid >> 2;          // 0..63
    const int ldSub = tid & 3;           // 16B chunk within row

    const __half* gA0 = Ag + (blockM + ldRow) * D_ + ldSub * 8;
    const __half* gA1 = Ag + (blockM + ldRow + 64) * D_ + ldSub * 8;
    const __half* gB0 = Bg + ((size_t)blockN + ldRow) * D_ + ldSub * 8;
    const __half* gB1 = Bg + ((size_t)blockN + ldRow + 64) * D_ + ldSub * 8;

    const int stA0 = ldRow * 4 + ldSub;
    const int stA1 = (ldRow + 64) * 4 + ldSub;

    // fragment offsets in uint2 units (uint4 index *2; +kg selects half)
    int aoff2[4][2], boff2[4];
    #pragma unroll
    for (int mi = 0; mi < 4; mi++)
        #pragma unroll
        for (int h = 0; h < 2; h++)
            aoff2[mi][h] = ((wm + mi * 16 + h * 8 + gID) * 4 + tig) * 2;
    #pragma unroll
    for (int ni = 0; ni < 4; ni++)
        boff2[ni] = ((wn + ni * 8 + gID) * 4 + tig) * 2;

    float c[4][4][4];
    #pragma unroll
    for (int i = 0; i < 4; i++)
        #pragma unroll
        for (int j = 0; j < 4; j++)
            #pragma unroll
            for (int k = 0; k < 4; k++) c[i][j][k] = 0.f;

    #define STAGE_LOAD(S)                                                    \
        do {                                                                 \
            uint4* sA = sm4 + (S) * STG_U4;                                  \
            uint4* sB = sm4 + SM_BOFF + (S) * STG_U4;                        \
            cp_async16(sA + stA0, gA0);                                      \
            cp_async16(sA + stA1, gA1);                                      \
            cp_async16(sB + stA0, gB0);                                      \
            cp_async16(sB + stA1, gB1);                                      \
            gA0 += BK; gA1 += BK; gB0 += BK; gB1 += BK;                      \
        } while (0)

    // uint2 view: index 2*u4 + kg. Pair = (pair t, pair t+4) of k-group kg.
    // Per accumulator: kg0 MMA then kg1 MMA (order identical to prior rounds).
    #define STAGE_COMPUTE(S)                                                 \
        do {                                                                 \
            const uint2* sA2 = (const uint2*)(sm4 + (S) * STG_U4);           \
            const uint2* sB2 = (const uint2*)(sm4 + SM_BOFF + (S) * STG_U4); \
            _Pragma("unroll")                                                \
            for (int kg = 0; kg < 2; ++kg) {                                 \
                uint2 A2[4][2];                                              \
                _Pragma("unroll")                                            \
                for (int mi = 0; mi < 4; mi++)                               \
                    _Pragma("unroll")                                        \
                    for (int h = 0; h < 2; h++)                              \
                        A2[mi][h] = sA2[aoff2[mi][h] + kg];                  \
                _Pragma("unroll")                                            \
                for (int ni = 0; ni < 4; ++ni) {                             \
                    const uint2 b = sB2[boff2[ni] + kg];                     \
                    _Pragma("unroll")                                        \
                    for (int mi = 0; mi < 4; ++mi)                           \
                        mma_f16(c[mi][ni], A2[mi][0].x, A2[mi][1].x,         \
                                A2[mi][0].y, A2[mi][1].y, b.x, b.y);         \
                }                                                            \
            }                                                                \
        } while (0)

    // prologue: tiles 0..2 -> stages 0..2
    STAGE_LOAD(0); CP_COMMIT();
    STAGE_LOAD(1); CP_COMMIT();
    STAGE_LOAD(2); CP_COMMIT();

    // main: 64 tiles, tile k in stage k%4; at iter k load tile k+3.
    for (int t = 0; t < KT / NSTG; ++t) {
        #pragma unroll
        for (int jj = 0; jj < NSTG; ++jj) {
            const int k = NSTG * t + jj;
            CP_WAIT2();            // tile k's group (committed 3 back) done
            __syncthreads();       // stage (jj+3)%4 fully consumed (tile k-1)
            if (k + 3 < KT) STAGE_LOAD((jj + 3) & 3);
            CP_COMMIT();
            STAGE_COMPUTE(jj);
        }
    }

    #undef STAGE_LOAD
    #undef STAGE_COMPUTE

    // ---------------- epilogue ----------------
    if (MODE == 0) {
        const int sect = blockN >> 11;          // 0:Q 1:K 2:V
        __half* dst = (sect == 0) ? g_Qh : ((sect == 1) ? g_Kh : g_Vh);
        const int colBase = blockN & (D_ - 1);
        #pragma unroll
        for (int mi = 0; mi < 4; ++mi) {
            const size_t rA = blockM + wm + mi * 16 + gID;
            const size_t rB = rA + 8;
            #pragma unroll
            for (int ni = 0; ni < 4; ++ni) {
                const int e  = blockN + wn + ni * 8 + tig * 2;
                const int el = colBase + wn + ni * 8 + tig * 2;
                const float bv0 = __ldg(&bias[e]);
                const float bv1 = __ldg(&bias[e + 1]);
                *(__half2*)(dst + rA * D_ + el) =
                    __floats2half2_rn(c[mi][ni][0] + bv0, c[mi][ni][1] + bv1);
                *(__half2*)(dst + rB * D_ + el) =
                    __floats2half2_rn(c[mi][ni][2] + bv0, c[mi][ni][3] + bv1);
            }
        }
    } else {
        float* dst = outParam;
        const int colBase = blockN;
        #pragma unroll
        for (int mi = 0; mi < 4; ++mi) {
            const size_t rA = blockM + wm + mi * 16 + gID;
            const size_t rB = rA + 8;
            #pragma unroll
            for (int ni = 0; ni < 4; ++ni) {
                const int e  = blockN + wn + ni * 8 + tig * 2;
                const int el = colBase + wn + ni * 8 + tig * 2;
                const float bv0 = __ldg(&bias[e]);
                const float bv1 = __ldg(&bias[e + 1]);
                const float2 x0 = *(const float2*)(Xres + rA * D_ + el);
                const float2 x1 = *(const float2*)(Xres + rB * D_ + el);
                *(float2*)(dst + rA * D_ + el) =
                    make_float2(c[mi][ni][0] + bv0 + x0.x, c[mi][ni][1] + bv1 + x0.y);
                *(float2*)(dst + rB * D_ + el) =
                    make_float2(c[mi][ni][2] + bv0 + x1.x, c[mi][ni][3] + bv1 + x1.y);
            }
        }
    }
}

// -------- reduction stage 1: per (batch, chunk) partial of fm(rope(K)) * V ---
__global__ __launch_bounds__(256)
void reduce_A_kernel()
{
    const int b     = blockIdx.x >> 7;
    const int chunk = blockIdx.x & (NCHUNK - 1);
    const int tid   = threadIdx.x;
    __shared__ float red[8];

    float acc[8];
    #pragma unroll
    for (int j = 0; j < 8; j++) acc[j] = 0.f;

    float invf[2];
    #pragma unroll
    for (int j = 0; j < 2; j++) {
        const int p = tid + 256 * j;
        invf[j] = exp2f((float)p * (float)NEG_L2T_OVER_512);
    }

    const int s0 = chunk * CHUNKS_S;
    for (int s = s0; s < s0 + CHUNKS_S; ++s) {
        const size_t rowoff = ((size_t)b * S_ + s) * D_;
        float kr[8];
        float sq = 0.f;
        #pragma unroll
        for (int j = 0; j < 4; ++j) {
            const int p = tid + 256 * j;
            const float2 kv = __half22float2(*(const __half2*)(g_Kh + rowoff + 2 * p));
            float x0 = kv.x, x1 = kv.y;
            if (j < 2) {
                float sn, cs;
                sincosf((float)s * invf[j], &sn, &cs);
                const float r0 = x0 * cs - x1 * sn;
                const float r1 = x1 * cs + x0 * sn;
                x0 = r0; x1 = r1;
            }
            kr[2 * j] = x0; kr[2 * j + 1] = x1;
            sq = fmaf(x0, x0, fmaf(x1, x1, sq));
        }
        #pragma unroll
        for (int o = 16; o; o >>= 1) sq += __shfl_xor_sync(0xffffffffu, sq, o);
        if ((tid & 31) == 0) red[tid >> 5] = sq;
        __syncthreads();
        const float tot = red[0] + red[1] + red[2] + red[3]
                        + red[4] + red[5] + red[6] + red[7];
        __syncthreads();
        const float inv_n = 1.f / fmaxf(sqrtf(tot), 1e-12f);

        #pragma unroll
        for (int j = 0; j < 4; ++j) {
            const int p = tid + 256 * j;
            const float2 vv = __half22float2(*(const __half2*)(g_Vh + rowoff + 2 * p));
            acc[2 * j]     = fmaf(kr[2 * j]     * inv_n, vv.x, acc[2 * j]);
            acc[2 * j + 1] = fmaf(kr[2 * j + 1] * inv_n, vv.y, acc[2 * j + 1]);
        }
    }
    float* dstp = g_Apart + ((size_t)b * NCHUNK + chunk) * D_;
    #pragma unroll
    for (int j = 0; j < 4; ++j) {
        const int p = tid + 256 * j;
        *(float2*)(dstp + 2 * p) = make_float2(acc[2 * j], acc[2 * j + 1]);
    }
}

// -------- reduction stage 2: fixed-order finalize ----------------------------
__global__ void finalize_A_kernel()
{
    const int i = blockIdx.x * 256 + threadIdx.x;
    const int b = i >> 11;
    const int d = i & (D_ - 1);
    float s = 0.f;
    for (int c = 0; c < NCHUNK; ++c)
        s += g_Apart[((size_t)b * NCHUNK + c) * D_ + d];
    g_A[i] = s;
}

// -------- Yb = fp16(A * rope(Q)), stored pair-PERMUTED for GEMM2 --------------
__global__ __launch_bounds__(256)
void yb_kernel()
{
    const int m = blockIdx.x;
    const int b = m >> 12;
    const int s = m & (S_ - 1);
    const int tid = threadIdx.x;
    const size_t rowoff = (size_t)m * D_;
    const float* Arow = g_A + b * D_;

    #pragma unroll
    for (int j = 0; j < 4; ++j) {
        const int p = tid + 256 * j;          // column pair index (0..1023)
        const float2 q = __half22float2(*(const __half2*)(g_Qh + rowoff + 2 * p));
        float x0 = q.x, x1 = q.y;
        if (j < 2) {
            const float invf = exp2f((float)p * (float)NEG_L2T_OVER_512);
            float sn, cs;
            sincosf((float)s * invf, &sn, &cs);
            const float r0 = x0 * cs - x1 * sn;
            const float r1 = x1 * cs + x0 * sn;
            x0 = r0; x1 = r1;
        }
        const float2 a = *(const float2*)(Arow + 2 * p);
        const int G  = p >> 4;
        const int pg = p & 15;
        const int slot = ((pg & 3) << 2) + ((pg >> 2) & 1) + ((pg >> 3) << 1);
        const unsigned hv = pack_h2(a.x * x0, a.y * x1);
        *(unsigned*)(&g_Yh[rowoff + G * 32 + slot * 2]) = hv;
    }
}

// ---------------- launch ------------------------------------------------------
extern "C" void kernel_launch(void* const* d_in, const int* in_sizes, int n_in,
                              void* d_out, int out_size)
{
    const float* X     = (const float*)d_in[0];   // [8,4096,2048]
    const float* W_in  = (const float*)d_in[1];   // [6144,2048]
    const float* b_in  = (const float*)d_in[2];   // [6144]
    const float* W_out = (const float*)d_in[3];   // [2048,2048]
    const float* b_out = (const float*)d_in[4];   // [2048]
    float* out = (float*)d_out;

    __half* xh; __half* w1h; __half* w2h;
    cudaGetSymbolAddress((void**)&xh,  g_Xh);
    cudaGetSymbolAddress((void**)&w1h, g_W1h);
    cudaGetSymbolAddress((void**)&w2h, g_W2h);

    cudaFuncSetAttribute(gemm_f16<0>, cudaFuncAttributeMaxDynamicSharedMemorySize, GEMM_SMEM);
    cudaFuncSetAttribute(gemm_f16<1>, cudaFuncAttributeMaxDynamicSharedMemorySize, GEMM_SMEM);

    // 0) fp32 -> permuted fp16 operands
    half_perm_kernel<<<(M_ * (D_/8)) / 256, 256>>>(X, xh, M_ * (D_/8));
    half_perm_kernel<<<(E1_ * (D_/8)) / 256, 256>>>(W_in, w1h, E1_ * (D_/8));
    half_perm_kernel<<<(D_ * (D_/8)) / 256, 256>>>(W_out, w2h, D_ * (D_/8));

    // 1) QKV = X @ W_in^T + b_in  ->  g_Qh, g_Kh, g_Vh (fp16)
    gemm_f16<0><<<dim3(E1_ / BN, M_ / BM), 256, GEMM_SMEM>>>(w1h, b_in, nullptr, nullptr);

    // 2) A = sum_s fm(rope(K)) * V
    reduce_A_kernel<<<B_ * NCHUNK, 256>>>();
    finalize_A_kernel<<<(B_ * D_) / 256, 256>>>();

    // 3) Yb = fp16(A ⊙ rope(Q))  (pair-permuted)
    yb_kernel<<<M_, 256>>>();

    // 4) out = Yb @ W_out^T + b_out + X
    gemm_f16<1><<<dim3(D_ / BN, M_ / BM), 256, GEMM_SMEM>>>(w2h, b_out, X, out);

    (void)in_sizes; (void)n_in; (void)out_size;
}

// round 14
// speedup vs baseline: 1.1039x; 1.0165x over previous
#include <cuda_runtime.h>
#include <cuda_fp16.h>
#include <cstdint>

// ---------------- problem constants ----------------
#define B_   8
#define S_   4096
#define D_   2048
#define M_   (B_*S_)        // 32768 tokens
#define E1_  (3*D_)         // 6144
#define NCHUNK 128
#define CHUNKS_S (S_/NCHUNK)   // 32

// ---------------- scratch (device globals) ----------------
__device__ __half g_Qh [67108864];   // fp16 Q (natural layout)
__device__ __half g_Kh [67108864];   // fp16 K
__device__ __half g_Vh [67108864];   // fp16 V
__device__ __half g_Yh [67108864];   // fp16, pair-permuted (GEMM2 A)
__device__ __half g_Xh [67108864];   // fp16(X), pair-permuted
__device__ __half g_W1h[(size_t)E1_ * D_];   // fp16(W_in), pair-permuted
__device__ __half g_W2h[(size_t)D_ * D_];    // fp16(W_out), pair-permuted
__device__ float  g_Apart[(size_t)B_ * NCHUNK * D_];
__device__ float  g_A[B_ * D_];
__device__ float2 g_rope[(size_t)S_ * 512];  // (cos, sin) per (s, pair p)

#define NEG_L2T_OVER_512 (-0.025952563241307517)

// ---------------- PTX helpers ----------------
__device__ __forceinline__ void cp_async16(void* sdst, const void* gsrc) {
    unsigned saddr = (unsigned)__cvta_generic_to_shared(sdst);
    asm volatile("cp.async.cg.shared.global [%0], [%1], 16;" :: "r"(saddr), "l"(gsrc));
}
#define CP_COMMIT() asm volatile("cp.async.commit_group;")
#define CP_WAIT2()  asm volatile("cp.async.wait_group 2;")

__device__ __forceinline__ unsigned pack_h2(float lo, float hi) {
    __half2 h = __floats2half2_rn(lo, hi);
    return *(unsigned*)&h;
}

__device__ __forceinline__ void mma_f16(float c[4], unsigned a0, unsigned a1,
                                        unsigned a2, unsigned a3,
                                        unsigned b0, unsigned b1) {
    asm volatile(
        "mma.sync.aligned.m16n8k16.row.col.f32.f16.f16.f32 "
        "{%0,%1,%2,%3},{%4,%5,%6,%7},{%8,%9},{%0,%1,%2,%3};"
        : "+f"(c[0]), "+f"(c[1]), "+f"(c[2]), "+f"(c[3])
        : "r"(a0), "r"(a1), "r"(a2), "r"(a3), "r"(b0), "r"(b1));
}

// -------- rope table: (cos, sin) for every (s, pair) — bit-identical trig ----
__global__ __launch_bounds__(256)
void build_rope_kernel()
{
    const int idx = blockIdx.x * 256 + threadIdx.x;   // s*512 + p
    const int s = idx >> 9;
    const int p = idx & 511;
    const float invf = exp2f((float)p * (float)NEG_L2T_OVER_512);
    float sn, cs;
    sincosf((float)s * invf, &sn, &cs);
    g_rope[idx] = make_float2(cs, sn);
}

// -------- fp32 -> permuted fp16 ------------------------------------------------
// Within each 32-wide k-group: pair p (cols 2p,2p+1), kg = p/8, pp = p%8.
// slot(kg,pp) = (pp&3)*4 + (pp>>2) + 2*kg. Output 16B chunk q of group holds
// kg0 pair q | kg0 pair q+4 | kg1 pair q | kg1 pair q+4.
__global__ __launch_bounds__(256)
void half_perm_kernel(const float* __restrict__ src, __half* __restrict__ dst,
                      int n16)
{
    const int c = blockIdx.x * 256 + threadIdx.x;
    if (c >= n16) return;
    const int row = c >> 8;
    const int cc  = c & 255;
    const int G   = cc >> 2;
    const int q   = cc & 3;
    const float* s = src + (size_t)row * D_ + G * 32 + q * 2;
    uint4 o;
    o.x = pack_h2(s[0],  s[1]);
    o.y = pack_h2(s[8],  s[9]);
    o.z = pack_h2(s[16], s[17]);
    o.w = pack_h2(s[24], s[25]);
    ((uint4*)dst)[c] = o;
}

// ---------------- FP16 GEMM: C[M,N] = A[M,K] * B[N,K]^T (+ epilogue) --------
// Round-13 config (best): 256 threads, 8 warps, warp tile 64x32 (2M x 4N),
// BK=32, 4-stage cp.async pipeline, two kg-passes with LDS.64 fragments.
// MODE 0: A=g_Xh -> g_Qh/g_Kh/g_Vh (fp16), bias=b_in.
// MODE 1: A=g_Yh -> d_out (fp32), epilogue adds b_out + X residual.
#define BM 128
#define BN 128
#define BK 32
#define KT (D_/BK)              // 64
#define NSTG 4
#define STG_U4 512              // uint4 per stage per operand (128 rows x 4)
#define SM_BOFF (NSTG*STG_U4)   // B region after 4 A stages
#define GEMM_SMEM (NSTG*STG_U4*2*16)   // 65536 bytes

template <int MODE>
__global__ __launch_bounds__(256, 2)
void gemm_f16(const __half* __restrict__ Bg,
              const float* __restrict__ bias,
              const float* __restrict__ Xres,
              float* __restrict__ outParam)
{
    extern __shared__ uint4 sm4[];

    const __half* __restrict__ Ag = (MODE == 0) ? g_Xh : g_Yh;

    const int tid  = threadIdx.x;
    const int lane = tid & 31;
    const int warp = tid >> 5;           // 0..7
    const int wm   = (warp >> 2) * 64;   // 2 warps in M
    const int wn   = (warp & 3) * 32;    // 4 warps in N
    const int gID  = lane >> 2;          // 0..7
    const int tig  = lane & 3;           // 0..3

    const int    blockN = blockIdx.x * BN;
    const size_t blockM = (size_t)blockIdx.y * BM;

    const int ldRow = tid >> 2;          // 0..63
    const int ldSub = tid & 3;           // 16B chunk within row

    const __half* gA0 = Ag + (blockM + ldRow) * D_ + ldSub * 8;
    const __half* gA1 = Ag + (blockM + ldRow + 64) * D_ + ldSub * 8;
    const __half* gB0 = Bg + ((size_t)blockN + ldRow) * D_ + ldSub * 8;
    const __half* gB1 = Bg + ((size_t)blockN + ldRow + 64) * D_ + ldSub * 8;

    const int stA0 = ldRow * 4 + ldSub;
    const int stA1 = (ldRow + 64) * 4 + ldSub;

    // fragment offsets in uint2 units (uint4 index *2; +kg selects half)
    int aoff2[4][2], boff2[4];
    #pragma unroll
    for (int mi = 0; mi < 4; mi++)
        #pragma unroll
        for (int h = 0; h < 2; h++)
            aoff2[mi][h] = ((wm + mi * 16 + h * 8 + gID) * 4 + tig) * 2;
    #pragma unroll
    for (int ni = 0; ni < 4; ni++)
        boff2[ni] = ((wn + ni * 8 + gID) * 4 + tig) * 2;

    float c[4][4][4];
    #pragma unroll
    for (int i = 0; i < 4; i++)
        #pragma unroll
        for (int j = 0; j < 4; j++)
            #pragma unroll
            for (int k = 0; k < 4; k++) c[i][j][k] = 0.f;

    #define STAGE_LOAD(S)                                                    \
        do {                                                                 \
            uint4* sA = sm4 + (S) * STG_U4;                                  \
            uint4* sB = sm4 + SM_BOFF + (S) * STG_U4;                        \
            cp_async16(sA + stA0, gA0);                                      \
            cp_async16(sA + stA1, gA1);                                      \
            cp_async16(sB + stA0, gB0);                                      \
            cp_async16(sB + stA1, gB1);                                      \
            gA0 += BK; gA1 += BK; gB0 += BK; gB1 += BK;                      \
        } while (0)

    #define STAGE_COMPUTE(S)                                                 \
        do {                                                                 \
            const uint2* sA2 = (const uint2*)(sm4 + (S) * STG_U4);           \
            const uint2* sB2 = (const uint2*)(sm4 + SM_BOFF + (S) * STG_U4); \
            _Pragma("unroll")                                                \
            for (int kg = 0; kg < 2; ++kg) {                                 \
                uint2 A2[4][2];                                              \
                _Pragma("unroll")                                            \
                for (int mi = 0; mi < 4; mi++)                               \
                    _Pragma("unroll")                                        \
                    for (int h = 0; h < 2; h++)                              \
                        A2[mi][h] = sA2[aoff2[mi][h] + kg];                  \
                _Pragma("unroll")                                            \
                for (int ni = 0; ni < 4; ++ni) {                             \
                    const uint2 b = sB2[boff2[ni] + kg];                     \
                    _Pragma("unroll")                                        \
                    for (int mi = 0; mi < 4; ++mi)                           \
                        mma_f16(c[mi][ni], A2[mi][0].x, A2[mi][1].x,         \
                                A2[mi][0].y, A2[mi][1].y, b.x, b.y);         \
                }                                                            \
            }                                                                \
        } while (0)

    STAGE_LOAD(0); CP_COMMIT();
    STAGE_LOAD(1); CP_COMMIT();
    STAGE_LOAD(2); CP_COMMIT();

    for (int t = 0; t < KT / NSTG; ++t) {
        #pragma unroll
        for (int jj = 0; jj < NSTG; ++jj) {
            const int k = NSTG * t + jj;
            CP_WAIT2();
            __syncthreads();
            if (k + 3 < KT) STAGE_LOAD((jj + 3) & 3);
            CP_COMMIT();
            STAGE_COMPUTE(jj);
        }
    }

    #undef STAGE_LOAD
    #undef STAGE_COMPUTE

    // ---------------- epilogue ----------------
    if (MODE == 0) {
        const int sect = blockN >> 11;          // 0:Q 1:K 2:V
        __half* dst = (sect == 0) ? g_Qh : ((sect == 1) ? g_Kh : g_Vh);
        const int colBase = blockN & (D_ - 1);
        #pragma unroll
        for (int mi = 0; mi < 4; ++mi) {
            const size_t rA = blockM + wm + mi * 16 + gID;
            const size_t rB = rA + 8;
            #pragma unroll
            for (int ni = 0; ni < 4; ++ni) {
                const int e  = blockN + wn + ni * 8 + tig * 2;
                const int el = colBase + wn + ni * 8 + tig * 2;
                const float bv0 = __ldg(&bias[e]);
                const float bv1 = __ldg(&bias[e + 1]);
                *(__half2*)(dst + rA * D_ + el) =
                    __floats2half2_rn(c[mi][ni][0] + bv0, c[mi][ni][1] + bv1);
                *(__half2*)(dst + rB * D_ + el) =
                    __floats2half2_rn(c[mi][ni][2] + bv0, c[mi][ni][3] + bv1);
            }
        }
    } else {
        float* dst = outParam;
        const int colBase = blockN;
        #pragma unroll
        for (int mi = 0; mi < 4; ++mi) {
            const size_t rA = blockM + wm + mi * 16 + gID;
            const size_t rB = rA + 8;
            #pragma unroll
            for (int ni = 0; ni < 4; ++ni) {
                const int e  = blockN + wn + ni * 8 + tig * 2;
                const int el = colBase + wn + ni * 8 + tig * 2;
                const float bv0 = __ldg(&bias[e]);
                const float bv1 = __ldg(&bias[e + 1]);
                const float2 x0 = *(const float2*)(Xres + rA * D_ + el);
                const float2 x1 = *(const float2*)(Xres + rB * D_ + el);
                *(float2*)(dst + rA * D_ + el) =
                    make_float2(c[mi][ni][0] + bv0 + x0.x, c[mi][ni][1] + bv1 + x0.y);
                *(float2*)(dst + rB * D_ + el) =
                    make_float2(c[mi][ni][2] + bv0 + x1.x, c[mi][ni][3] + bv1 + x1.y);
            }
        }
    }
}

// -------- reduction stage 1: per (batch, chunk) partial of fm(rope(K)) * V ---
// rope trig read from g_rope table (bit-identical values, no sincosf).
__global__ __launch_bounds__(256)
void reduce_A_kernel()
{
    const int b     = blockIdx.x >> 7;
    const int chunk = blockIdx.x & (NCHUNK - 1);
    const int tid   = threadIdx.x;
    __shared__ float red[8];

    float acc[8];
    #pragma unroll
    for (int j = 0; j < 8; j++) acc[j] = 0.f;

    const int s0 = chunk * CHUNKS_S;
    for (int s = s0; s < s0 + CHUNKS_S; ++s) {
        const size_t rowoff = ((size_t)b * S_ + s) * D_;
        const float2* trow = g_rope + (size_t)s * 512;
        float kr[8];
        float sq = 0.f;
        #pragma unroll
        for (int j = 0; j < 4; ++j) {
            const int p = tid + 256 * j;
            const float2 kv = __half22float2(*(const __half2*)(g_Kh + rowoff + 2 * p));
            float x0 = kv.x, x1 = kv.y;
            if (j < 2) {
                const float2 t = trow[p];      // (cos, sin)
                const float r0 = x0 * t.x - x1 * t.y;
                const float r1 = x1 * t.x + x0 * t.y;
                x0 = r0; x1 = r1;
            }
            kr[2 * j] = x0; kr[2 * j + 1] = x1;
            sq = fmaf(x0, x0, fmaf(x1, x1, sq));
        }
        #pragma unroll
        for (int o = 16; o; o >>= 1) sq += __shfl_xor_sync(0xffffffffu, sq, o);
        if ((tid & 31) == 0) red[tid >> 5] = sq;
        __syncthreads();
        const float tot = red[0] + red[1] + red[2] + red[3]
                        + red[4] + red[5] + red[6] + red[7];
        __syncthreads();
        const float inv_n = 1.f / fmaxf(sqrtf(tot), 1e-12f);

        #pragma unroll
        for (int j = 0; j < 4; ++j) {
            const int p = tid + 256 * j;
            const float2 vv = __half22float2(*(const __half2*)(g_Vh + rowoff + 2 * p));
            acc[2 * j]     = fmaf(kr[2 * j]     * inv_n, vv.x, acc[2 * j]);
            acc[2 * j + 1] = fmaf(kr[2 * j + 1] * inv_n, vv.y, acc[2 * j + 1]);
        }
    }
    float* dstp = g_Apart + ((size_t)b * NCHUNK + chunk) * D_;
    #pragma unroll
    for (int j = 0; j < 4; ++j) {
        const int p = tid + 256 * j;
        *(float2*)(dstp + 2 * p) = make_float2(acc[2 * j], acc[2 * j + 1]);
    }
}

// -------- reduction stage 2: fixed-order finalize ----------------------------
__global__ void finalize_A_kernel()
{
    const int i = blockIdx.x * 256 + threadIdx.x;
    const int b = i >> 11;
    const int d = i & (D_ - 1);
    float s = 0.f;
    for (int c = 0; c < NCHUNK; ++c)
        s += g_Apart[((size_t)b * NCHUNK + c) * D_ + d];
    g_A[i] = s;
}

// -------- Yb = fp16(A * rope(Q)), stored pair-PERMUTED for GEMM2 --------------
// rope trig read from g_rope table (bit-identical values, no sincosf).
__global__ __launch_bounds__(256)
void yb_kernel()
{
    const int m = blockIdx.x;
    const int b = m >> 12;
    const int s = m & (S_ - 1);
    const int tid = threadIdx.x;
    const size_t rowoff = (size_t)m * D_;
    const float* Arow = g_A + b * D_;
    const float2* trow = g_rope + (size_t)s * 512;

    #pragma unroll
    for (int j = 0; j < 4; ++j) {
        const int p = tid + 256 * j;          // column pair index (0..1023)
        const float2 q = __half22float2(*(const __half2*)(g_Qh + rowoff + 2 * p));
        float x0 = q.x, x1 = q.y;
        if (j < 2) {
            const float2 t = trow[p];          // (cos, sin)
            const float r0 = x0 * t.x - x1 * t.y;
            const float r1 = x1 * t.x + x0 * t.y;
            x0 = r0; x1 = r1;
        }
        const float2 a = *(const float2*)(Arow + 2 * p);
        const int G  = p >> 4;
        const int pg = p & 15;
        const int slot = ((pg & 3) << 2) + ((pg >> 2) & 1) + ((pg >> 3) << 1);
        const unsigned hv = pack_h2(a.x * x0, a.y * x1);
        *(unsigned*)(&g_Yh[rowoff + G * 32 + slot * 2]) = hv;
    }
}

// ---------------- launch ------------------------------------------------------
extern "C" void kernel_launch(void* const* d_in, const int* in_sizes, int n_in,
                              void* d_out, int out_size)
{
    const float* X     = (const float*)d_in[0];   // [8,4096,2048]
    const float* W_in  = (const float*)d_in[1];   // [6144,2048]
    const float* b_in  = (const float*)d_in[2];   // [6144]
    const float* W_out = (const float*)d_in[3];   // [2048,2048]
    const float* b_out = (const float*)d_in[4];   // [2048]
    float* out = (float*)d_out;

    __half* xh; __half* w1h; __half* w2h;
    cudaGetSymbolAddress((void**)&xh,  g_Xh);
    cudaGetSymbolAddress((void**)&w1h, g_W1h);
    cudaGetSymbolAddress((void**)&w2h, g_W2h);

    cudaFuncSetAttribute(gemm_f16<0>, cudaFuncAttributeMaxDynamicSharedMemorySize, GEMM_SMEM);
    cudaFuncSetAttribute(gemm_f16<1>, cudaFuncAttributeMaxDynamicSharedMemorySize, GEMM_SMEM);

    // 0) rope table + fp32 -> permuted fp16 operands
    build_rope_kernel<<<(S_ * 512) / 256, 256>>>();
    half_perm_kernel<<<(M_ * (D_/8)) / 256, 256>>>(X, xh, M_ * (D_/8));
    half_perm_kernel<<<(E1_ * (D_/8)) / 256, 256>>>(W_in, w1h, E1_ * (D_/8));
    half_perm_kernel<<<(D_ * (D_/8)) / 256, 256>>>(W_out, w2h, D_ * (D_/8));

    // 1) QKV = X @ W_in^T + b_in  ->  g_Qh, g_Kh, g_Vh (fp16)
    gemm_f16<0><<<dim3(E1_ / BN, M_ / BM), 256, GEMM_SMEM>>>(w1h, b_in, nullptr, nullptr);

    // 2) A = sum_s fm(rope(K)) * V
    reduce_A_kernel<<<B_ * NCHUNK, 256>>>();
    finalize_A_kernel<<<(B_ * D_) / 256, 256>>>();

    // 3) Yb = fp16(A ⊙ rope(Q))  (pair-permuted)
    yb_kernel<<<M_, 256>>>();

    // 4) out = Yb @ W_out^T + b_out + X
    gemm_f16<1><<<dim3(D_ / BN, M_ / BM), 256, GEMM_SMEM>>>(w2h, b_out, X, out);

    (void)in_sizes; (void)n_in; (void)out_size;
}

// round 15
// speedup vs baseline: 1.1102x; 1.0057x over previous
#include <cuda_runtime.h>
#include <cuda_fp16.h>
#include <cstdint>

// ---------------- problem constants ----------------
#define B_   8
#define S_   4096
#define D_   2048
#define M_   (B_*S_)        // 32768 tokens
#define E1_  (3*D_)         // 6144
#define NCHUNK 128
#define CHUNKS_S (S_/NCHUNK)   // 32

// ---------------- scratch (device globals) ----------------
__device__ __half g_Qh [67108864];   // fp16 Q (natural layout)
__device__ __half g_Kh [67108864];   // fp16 K
__device__ __half g_Vh [67108864];   // fp16 V
__device__ __half g_Yh [67108864];   // fp16, pair-permuted (GEMM2 A)
__device__ __half g_Xh [67108864];   // fp16(X), pair-permuted
__device__ __half g_W1h[(size_t)E1_ * D_];   // fp16(W_in), pair-permuted
__device__ __half g_W2h[(size_t)D_ * D_];    // fp16(W_out), pair-permuted
__device__ float  g_Apart[(size_t)B_ * NCHUNK * D_];
__device__ float  g_A[B_ * D_];
__device__ float2 g_rope[(size_t)S_ * 512];  // (cos, sin) per (s, pair p)

#define NEG_L2T_OVER_512 (-0.025952563241307517)

// ---------------- PTX helpers ----------------
__device__ __forceinline__ void cp_async16(void* sdst, const void* gsrc) {
    unsigned saddr = (unsigned)__cvta_generic_to_shared(sdst);
    asm volatile("cp.async.cg.shared.global [%0], [%1], 16;" :: "r"(saddr), "l"(gsrc));
}
#define CP_COMMIT() asm volatile("cp.async.commit_group;")
#define CP_WAIT2()  asm volatile("cp.async.wait_group 2;")

__device__ __forceinline__ unsigned pack_h2(float lo, float hi) {
    __half2 h = __floats2half2_rn(lo, hi);
    return *(unsigned*)&h;
}

__device__ __forceinline__ void mma_f16(float c[4], unsigned a0, unsigned a1,
                                        unsigned a2, unsigned a3,
                                        unsigned b0, unsigned b1) {
    asm volatile(
        "mma.sync.aligned.m16n8k16.row.col.f32.f16.f16.f32 "
        "{%0,%1,%2,%3},{%4,%5,%6,%7},{%8,%9},{%0,%1,%2,%3};"
        : "+f"(c[0]), "+f"(c[1]), "+f"(c[2]), "+f"(c[3])
        : "r"(a0), "r"(a1), "r"(a2), "r"(a3), "r"(b0), "r"(b1));
}

// -------- rope table: (cos, sin) for every (s, pair) — bit-identical trig ----
__global__ __launch_bounds__(256)
void build_rope_kernel()
{
    const int idx = blockIdx.x * 256 + threadIdx.x;   // s*512 + p
    const int s = idx >> 9;
    const int p = idx & 511;
    const float invf = exp2f((float)p * (float)NEG_L2T_OVER_512);
    float sn, cs;
    sincosf((float)s * invf, &sn, &cs);
    g_rope[idx] = make_float2(cs, sn);
}

// -------- fp32 -> permuted fp16 ------------------------------------------------
// Within each 32-wide k-group: pair p (cols 2p,2p+1), kg = p/8, pp = p%8.
// slot(kg,pp) = (pp&3)*4 + (pp>>2) + 2*kg. Output 16B chunk q of group holds
// kg0 pair q | kg0 pair q+4 | kg1 pair q | kg1 pair q+4.
__global__ __launch_bounds__(256)
void half_perm_kernel(const float* __restrict__ src, __half* __restrict__ dst,
                      int n16)
{
    const int c = blockIdx.x * 256 + threadIdx.x;
    if (c >= n16) return;
    const int row = c >> 8;
    const int cc  = c & 255;
    const int G   = cc >> 2;
    const int q   = cc & 3;
    const float* s = src + (size_t)row * D_ + G * 32 + q * 2;
    uint4 o;
    o.x = pack_h2(s[0],  s[1]);
    o.y = pack_h2(s[8],  s[9]);
    o.z = pack_h2(s[16], s[17]);
    o.w = pack_h2(s[24], s[25]);
    ((uint4*)dst)[c] = o;
}

// ---------------- FP16 GEMM: C[M,N] = A[M,K] * B[N,K]^T (+ epilogue) --------
// Round-13 config (best): 256 threads, 8 warps, warp tile 64x32 (2M x 4N),
// BK=32, 4-stage cp.async pipeline, two kg-passes with LDS.64 fragments.
// MODE 0: A=g_Xh -> g_Qh/g_Kh/g_Vh (fp16), bias=b_in.
// MODE 1: A=g_Yh -> d_out (fp32), epilogue adds b_out + X residual.
#define BM 128
#define BN 128
#define BK 32
#define KT (D_/BK)              // 64
#define NSTG 4
#define STG_U4 512              // uint4 per stage per operand (128 rows x 4)
#define SM_BOFF (NSTG*STG_U4)   // B region after 4 A stages
#define GEMM_SMEM (NSTG*STG_U4*2*16)   // 65536 bytes

template <int MODE>
__global__ __launch_bounds__(256, 2)
void gemm_f16(const __half* __restrict__ Bg,
              const float* __restrict__ bias,
              const float* __restrict__ Xres,
              float* __restrict__ outParam)
{
    extern __shared__ uint4 sm4[];

    const __half* __restrict__ Ag = (MODE == 0) ? g_Xh : g_Yh;

    const int tid  = threadIdx.x;
    const int lane = tid & 31;
    const int warp = tid >> 5;           // 0..7
    const int wm   = (warp >> 2) * 64;   // 2 warps in M
    const int wn   = (warp & 3) * 32;    // 4 warps in N
    const int gID  = lane >> 2;          // 0..7
    const int tig  = lane & 3;           // 0..3

    const int    blockN = blockIdx.x * BN;
    const size_t blockM = (size_t)blockIdx.y * BM;

    const int ldRow = tid >> 2;          // 0..63
    const int ldSub = tid & 3;           // 16B chunk within row

    const __half* gA0 = Ag + (blockM + ldRow) * D_ + ldSub * 8;
    const __half* gA1 = Ag + (blockM + ldRow + 64) * D_ + ldSub * 8;
    const __half* gB0 = Bg + ((size_t)blockN + ldRow) * D_ + ldSub * 8;
    const __half* gB1 = Bg + ((size_t)blockN + ldRow + 64) * D_ + ldSub * 8;

    const int stA0 = ldRow * 4 + ldSub;
    const int stA1 = (ldRow + 64) * 4 + ldSub;

    // fragment offsets in uint2 units (uint4 index *2; +kg selects half)
    int aoff2[4][2], boff2[4];
    #pragma unroll
    for (int mi = 0; mi < 4; mi++)
        #pragma unroll
        for (int h = 0; h < 2; h++)
            aoff2[mi][h] = ((wm + mi * 16 + h * 8 + gID) * 4 + tig) * 2;
    #pragma unroll
    for (int ni = 0; ni < 4; ni++)
        boff2[ni] = ((wn + ni * 8 + gID) * 4 + tig) * 2;

    float c[4][4][4];
    #pragma unroll
    for (int i = 0; i < 4; i++)
        #pragma unroll
        for (int j = 0; j < 4; j++)
            #pragma unroll
            for (int k = 0; k < 4; k++) c[i][j][k] = 0.f;

    #define STAGE_LOAD(S)                                                    \
        do {                                                                 \
            uint4* sA = sm4 + (S) * STG_U4;                                  \
            uint4* sB = sm4 + SM_BOFF + (S) * STG_U4;                        \
            cp_async16(sA + stA0, gA0);                                      \
            cp_async16(sA + stA1, gA1);                                      \
            cp_async16(sB + stA0, gB0);                                      \
            cp_async16(sB + stA1, gB1);                                      \
            gA0 += BK; gA1 += BK; gB0 += BK; gB1 += BK;                      \
        } while (0)

    #define STAGE_COMPUTE(S)                                                 \
        do {                                                                 \
            const uint2* sA2 = (const uint2*)(sm4 + (S) * STG_U4);           \
            const uint2* sB2 = (const uint2*)(sm4 + SM_BOFF + (S) * STG_U4); \
            _Pragma("unroll")                                                \
            for (int kg = 0; kg < 2; ++kg) {                                 \
                uint2 A2[4][2];                                              \
                _Pragma("unroll")                                            \
                for (int mi = 0; mi < 4; mi++)                               \
                    _Pragma("unroll")                                        \
                    for (int h = 0; h < 2; h++)                              \
                        A2[mi][h] = sA2[aoff2[mi][h] + kg];                  \
                _Pragma("unroll")                                            \
                for (int ni = 0; ni < 4; ++ni) {                             \
                    const uint2 b = sB2[boff2[ni] + kg];                     \
                    _Pragma("unroll")                                        \
                    for (int mi = 0; mi < 4; ++mi)                           \
                        mma_f16(c[mi][ni], A2[mi][0].x, A2[mi][1].x,         \
                                A2[mi][0].y, A2[mi][1].y, b.x, b.y);         \
                }                                                            \
            }                                                                \
        } while (0)

    STAGE_LOAD(0); CP_COMMIT();
    STAGE_LOAD(1); CP_COMMIT();
    STAGE_LOAD(2); CP_COMMIT();

    for (int t = 0; t < KT / NSTG; ++t) {
        #pragma unroll
        for (int jj = 0; jj < NSTG; ++jj) {
            const int k = NSTG * t + jj;
            CP_WAIT2();
            __syncthreads();
            if (k + 3 < KT) STAGE_LOAD((jj + 3) & 3);
            CP_COMMIT();
            STAGE_COMPUTE(jj);
        }
    }

    #undef STAGE_LOAD
    #undef STAGE_COMPUTE

    // ---------------- epilogue ----------------
    if (MODE == 0) {
        const int sect = blockN >> 11;          // 0:Q 1:K 2:V
        __half* dst = (sect == 0) ? g_Qh : ((sect == 1) ? g_Kh : g_Vh);
        const int colBase = blockN & (D_ - 1);
        #pragma unroll
        for (int mi = 0; mi < 4; ++mi) {
            const size_t rA = blockM + wm + mi * 16 + gID;
            const size_t rB = rA + 8;
            #pragma unroll
            for (int ni = 0; ni < 4; ++ni) {
                const int e  = blockN + wn + ni * 8 + tig * 2;
                const int el = colBase + wn + ni * 8 + tig * 2;
                const float bv0 = __ldg(&bias[e]);
                const float bv1 = __ldg(&bias[e + 1]);
                *(__half2*)(dst + rA * D_ + el) =
                    __floats2half2_rn(c[mi][ni][0] + bv0, c[mi][ni][1] + bv1);
                *(__half2*)(dst + rB * D_ + el) =
                    __floats2half2_rn(c[mi][ni][2] + bv0, c[mi][ni][3] + bv1);
            }
        }
    } else {
        float* dst = outParam;
        const int colBase = blockN;
        #pragma unroll
        for (int mi = 0; mi < 4; ++mi) {
            const size_t rA = blockM + wm + mi * 16 + gID;
            const size_t rB = rA + 8;
            #pragma unroll
            for (int ni = 0; ni < 4; ++ni) {
                const int e  = blockN + wn + ni * 8 + tig * 2;
                const int el = colBase + wn + ni * 8 + tig * 2;
                const float bv0 = __ldg(&bias[e]);
                const float bv1 = __ldg(&bias[e + 1]);
                const float2 x0 = *(const float2*)(Xres + rA * D_ + el);
                const float2 x1 = *(const float2*)(Xres + rB * D_ + el);
                *(float2*)(dst + rA * D_ + el) =
                    make_float2(c[mi][ni][0] + bv0 + x0.x, c[mi][ni][1] + bv1 + x0.y);
                *(float2*)(dst + rB * D_ + el) =
                    make_float2(c[mi][ni][2] + bv0 + x1.x, c[mi][ni][3] + bv1 + x1.y);
            }
        }
    }
}

// -------- reduction stage 1: per (batch, chunk) partial of fm(rope(K)) * V ---
// 4 rows per iteration, ONE __syncthreads per iteration (double-buffered red):
// writes to red[it&1] are WAR-separated from the previous read of that buffer
// by the intervening iteration's barrier. FP order per row unchanged
// (shfl tree + warps 0..7 sum + s-ascending accumulation) -> bit-identical.
__global__ __launch_bounds__(256)
void reduce_A_kernel()
{
    const int b     = blockIdx.x >> 7;
    const int chunk = blockIdx.x & (NCHUNK - 1);
    const int tid   = threadIdx.x;
    const int wid   = tid >> 5;
    __shared__ float red[2][32];        // [buf][r*8 + warp]

    float acc[8];
    #pragma unroll
    for (int j = 0; j < 8; j++) acc[j] = 0.f;

    const int s0 = chunk * CHUNKS_S;
    for (int it = 0; it < CHUNKS_S / 4; ++it) {
        const int sb = s0 + it * 4;
        const int buf = it & 1;

        float kr[4][8];
        float sq[4];
        #pragma unroll
        for (int r = 0; r < 4; ++r) {
            const int s = sb + r;
            const size_t rowoff = ((size_t)b * S_ + s) * D_;
            const float2* trow = g_rope + (size_t)s * 512;
            float sqr = 0.f;
            #pragma unroll
            for (int j = 0; j < 4; ++j) {
                const int p = tid + 256 * j;
                const float2 kv = __half22float2(*(const __half2*)(g_Kh + rowoff + 2 * p));
                float x0 = kv.x, x1 = kv.y;
                if (j < 2) {
                    const float2 t = trow[p];      // (cos, sin)
                    const float r0 = x0 * t.x - x1 * t.y;
                    const float r1 = x1 * t.x + x0 * t.y;
                    x0 = r0; x1 = r1;
                }
                kr[r][2 * j] = x0; kr[r][2 * j + 1] = x1;
                sqr = fmaf(x0, x0, fmaf(x1, x1, sqr));
            }
            sq[r] = sqr;
        }
        #pragma unroll
        for (int r = 0; r < 4; ++r) {
            float v = sq[r];
            #pragma unroll
            for (int o = 16; o; o >>= 1) v += __shfl_xor_sync(0xffffffffu, v, o);
            if ((tid & 31) == 0) red[buf][r * 8 + wid] = v;
        }
        __syncthreads();

        #pragma unroll
        for (int r = 0; r < 4; ++r) {
            const int s = sb + r;
            const size_t rowoff = ((size_t)b * S_ + s) * D_;
            const float tot = red[buf][r*8+0] + red[buf][r*8+1] + red[buf][r*8+2]
                            + red[buf][r*8+3] + red[buf][r*8+4] + red[buf][r*8+5]
                            + red[buf][r*8+6] + red[buf][r*8+7];
            const float inv_n = 1.f / fmaxf(sqrtf(tot), 1e-12f);
            #pragma unroll
            for (int j = 0; j < 4; ++j) {
                const int p = tid + 256 * j;
                const float2 vv = __half22float2(*(const __half2*)(g_Vh + rowoff + 2 * p));
                acc[2 * j]     = fmaf(kr[r][2 * j]     * inv_n, vv.x, acc[2 * j]);
                acc[2 * j + 1] = fmaf(kr[r][2 * j + 1] * inv_n, vv.y, acc[2 * j + 1]);
            }
        }
    }
    float* dstp = g_Apart + ((size_t)b * NCHUNK + chunk) * D_;
    #pragma unroll
    for (int j = 0; j < 4; ++j) {
        const int p = tid + 256 * j;
        *(float2*)(dstp + 2 * p) = make_float2(acc[2 * j], acc[2 * j + 1]);
    }
}

// -------- reduction stage 2: fixed-order finalize ----------------------------
__global__ void finalize_A_kernel()
{
    const int i = blockIdx.x * 256 + threadIdx.x;
    const int b = i >> 11;
    const int d = i & (D_ - 1);
    float s = 0.f;
    for (int c = 0; c < NCHUNK; ++c)
        s += g_Apart[((size_t)b * NCHUNK + c) * D_ + d];
    g_A[i] = s;
}

// -------- Yb = fp16(A * rope(Q)), stored pair-PERMUTED for GEMM2 --------------
__global__ __launch_bounds__(256)
void yb_kernel()
{
    const int m = blockIdx.x;
    const int b = m >> 12;
    const int s = m & (S_ - 1);
    const int tid = threadIdx.x;
    const size_t rowoff = (size_t)m * D_;
    const float* Arow = g_A + b * D_;
    const float2* trow = g_rope + (size_t)s * 512;

    #pragma unroll
    for (int j = 0; j < 4; ++j) {
        const int p = tid + 256 * j;          // column pair index (0..1023)
        const float2 q = __half22float2(*(const __half2*)(g_Qh + rowoff + 2 * p));
        float x0 = q.x, x1 = q.y;
        if (j < 2) {
            const float2 t = trow[p];          // (cos, sin)
            const float r0 = x0 * t.x - x1 * t.y;
            const float r1 = x1 * t.x + x0 * t.y;
            x0 = r0; x1 = r1;
        }
        const float2 a = *(const float2*)(Arow + 2 * p);
        const int G  = p >> 4;
        const int pg = p & 15;
        const int slot = ((pg & 3) << 2) + ((pg >> 2) & 1) + ((pg >> 3) << 1);
        const unsigned hv = pack_h2(a.x * x0, a.y * x1);
        *(unsigned*)(&g_Yh[rowoff + G * 32 + slot * 2]) = hv;
    }
}

// ---------------- launch ------------------------------------------------------
extern "C" void kernel_launch(void* const* d_in, const int* in_sizes, int n_in,
                              void* d_out, int out_size)
{
    const float* X     = (const float*)d_in[0];   // [8,4096,2048]
    const float* W_in  = (const float*)d_in[1];   // [6144,2048]
    const float* b_in  = (const float*)d_in[2];   // [6144]
    const float* W_out = (const float*)d_in[3];   // [2048,2048]
    const float* b_out = (const float*)d_in[4];   // [2048]
    float* out = (float*)d_out;

    __half* xh; __half* w1h; __half* w2h;
    cudaGetSymbolAddress((void**)&xh,  g_Xh);
    cudaGetSymbolAddress((void**)&w1h, g_W1h);
    cudaGetSymbolAddress((void**)&w2h, g_W2h);

    cudaFuncSetAttribute(gemm_f16<0>, cudaFuncAttributeMaxDynamicSharedMemorySize, GEMM_SMEM);
    cudaFuncSetAttribute(gemm_f16<1>, cudaFuncAttributeMaxDynamicSharedMemorySize, GEMM_SMEM);

    // 0) rope table + fp32 -> permuted fp16 operands
    build_rope_kernel<<<(S_ * 512) / 256, 256>>>();
    half_perm_kernel<<<(M_ * (D_/8)) / 256, 256>>>(X, xh, M_ * (D_/8));
    half_perm_kernel<<<(E1_ * (D_/8)) / 256, 256>>>(W_in, w1h, E1_ * (D_/8));
    half_perm_kernel<<<(D_ * (D_/8)) / 256, 256>>>(W_out, w2h, D_ * (D_/8));

    // 1) QKV = X @ W_in^T + b_in  ->  g_Qh, g_Kh, g_Vh (fp16)
    gemm_f16<0><<<dim3(E1_ / BN, M_ / BM), 256, GEMM_SMEM>>>(w1h, b_in, nullptr, nullptr);

    // 2) A = sum_s fm(rope(K)) * V
    reduce_A_kernel<<<B_ * NCHUNK, 256>>>();
    finalize_A_kernel<<<(B_ * D_) / 256, 256>>>();

    // 3) Yb = fp16(A ⊙ rope(Q))  (pair-permuted)
    yb_kernel<<<M_, 256>>>();

    // 4) out = Yb @ W_out^T + b_out + X
    gemm_f16<1><<<dim3(D_ / BN, M_ / BM), 256, GEMM_SMEM>>>(w2h, b_out, X, out);

    (void)in_sizes; (void)n_in; (void)out_size;
}